// round 9
// baseline (speedup 1.0000x reference)
#include <cuda_runtime.h>
#include <cuda_bf16.h>
#include <cstdint>

// Problem constants
#define BSESS 1024
#define NNODE 32
#define SLEN  50
#define HD    256
#define VOC   50000

// Scores GEMM config: C[1024,50000] split-bf16.
// 8 B-chunks of 64 k: kc<4 -> Bh (MMA with Ah AND Al), kc>=4 -> Bl (Ah only).
#define KC      64
#define NCHUNK  8
#define TILEB   16384              // 128 rows x 128 B
#define STAGE3  (3*TILEB)          // B + Ah + Al = 48 KB
#define SMEM_SZ (2*STAGE3)         // 96 KB double buffered

// Prep kernel geometry: 128 chain CTAs + 384 conv CTAs
#define CHAIN_CTAS 128
#define CONV_CTAS  384

// Scratch
__device__ float g_sh[BSESS*HD];
__device__ __nv_bfloat16 g_Bh[(size_t)VOC*HD];
__device__ __nv_bfloat16 g_Bl[(size_t)VOC*HD];
__device__ __nv_bfloat16 g_Ah[BSESS*HD];
__device__ __nv_bfloat16 g_Al[BSESS*HD];

// ---------------------------------------------------------------------------
// Helpers (baseline ISA only)
// ---------------------------------------------------------------------------
__device__ __forceinline__ uint32_t smem_u32(const void* p) {
    uint32_t a;
    asm("{ .reg .u64 t; cvta.to.shared.u64 t, %1; cvt.u32.u64 %0, t; }"
        : "=r"(a) : "l"(p));
    return a;
}
__device__ __forceinline__ void cp16(uint32_t dst, const void* src) {
    asm volatile("cp.async.cg.shared.global [%0], [%1], 16;"
                 :: "r"(dst), "l"(src));
}
#define CP_COMMIT() asm volatile("cp.async.commit_group;" ::: "memory")
#define CP_WAIT(n)  asm volatile("cp.async.wait_group %0;" :: "n"(n) : "memory")

__device__ __forceinline__ uint32_t sw128(uint32_t x) {
    return x ^ ((x >> 3) & 0x70);
}
__device__ __forceinline__ void ldsm4(uint32_t* r, uint32_t addr) {
    asm volatile("ldmatrix.sync.aligned.m8n8.x4.shared.b16 {%0,%1,%2,%3}, [%4];"
                 : "=r"(r[0]), "=r"(r[1]), "=r"(r[2]), "=r"(r[3]) : "r"(addr));
}
__device__ __forceinline__ void mma16816(float* c, const uint32_t* a,
                                         const uint32_t* b) {
    asm volatile(
        "mma.sync.aligned.m16n8k16.row.col.f32.bf16.bf16.f32 "
        "{%0,%1,%2,%3}, {%4,%5,%6,%7}, {%8,%9}, {%0,%1,%2,%3};"
        : "+f"(c[0]), "+f"(c[1]), "+f"(c[2]), "+f"(c[3])
        : "r"(a[0]), "r"(a[1]), "r"(a[2]), "r"(a[3]), "r"(b[0]), "r"(b[1]));
}

// ---------------------------------------------------------------------------
// Prep kernel: CTAs [0,128) run the fused SAN chain (vn -> 3 SAN blocks ->
// W3 -> s_h + A-side bf16 split); CTAs [128,512) run the B-side fp32->bf16
// hi/lo split in grid-stride. Independent work, overlapped in one launch.
// ---------------------------------------------------------------------------
__global__ void __launch_bounds__(256, 2)
prep_kernel(const float* __restrict__ node_emb,
            const float* __restrict__ itemset_len,
            const int*   __restrict__ sequence,
            const float* __restrict__ emb_weight,
            const float* __restrict__ Wv,  const float* __restrict__ bv,
            const float* __restrict__ Wo,  const float* __restrict__ bo,
            const float* __restrict__ d1w, const float* __restrict__ d1b,
            const float* __restrict__ d2w, const float* __restrict__ d2b,
            const float* __restrict__ W3w, const float* __restrict__ W3b) {
    int tid = threadIdx.x;

    if (blockIdx.x >= CHAIN_CTAS) {
        // ---- B-side split: grid-stride over VOC*HD/4 float4s ----
        int cid = blockIdx.x - CHAIN_CTAS;
        const int n4 = VOC*HD/4;
        for (int i = cid*256 + tid; i < n4; i += CONV_CTAS*256) {
            float4 v = ((const float4*)emb_weight)[i];
            __nv_bfloat16 h0 = __float2bfloat16(v.x), h1 = __float2bfloat16(v.y),
                          h2 = __float2bfloat16(v.z), h3 = __float2bfloat16(v.w);
            __nv_bfloat16 l0 = __float2bfloat16(v.x - __bfloat162float(h0));
            __nv_bfloat16 l1 = __float2bfloat16(v.y - __bfloat162float(h1));
            __nv_bfloat16 l2 = __float2bfloat16(v.z - __bfloat162float(h2));
            __nv_bfloat16 l3 = __float2bfloat16(v.w - __bfloat162float(h3));
            ((__nv_bfloat162*)g_Bh)[i*2+0] = __nv_bfloat162(h0, h1);
            ((__nv_bfloat162*)g_Bh)[i*2+1] = __nv_bfloat162(h2, h3);
            ((__nv_bfloat162*)g_Bl)[i*2+0] = __nv_bfloat162(l0, l1);
            ((__nv_bfloat162*)g_Bl)[i*2+1] = __nv_bfloat162(l2, l3);
        }
        return;
    }

    // ---- Chain part ----
    __shared__ float sv[8*HD];
    __shared__ float sx[8*HD];
    __shared__ float sa[8*HD];
    __shared__ float st[8*HD];
    int w = tid >> 5, lane = tid & 31;
    int b0 = blockIdx.x * 8;

    // v_n gather: warp w -> row w
    {
        int b = b0 + w;
        int t = b*SLEN + (SLEN-1);
        int s0 = sequence[t*3+0], s1 = sequence[t*3+1], s2 = sequence[t*3+2];
        float inv = 1.f / itemset_len[t];
        const float* base = node_emb + (size_t)b*NNODE*HD;
        #pragma unroll
        for (int p = 0; p < 2; p++) {
            int c = lane*8 + p*4;
            float4 acc = make_float4(0.f, 0.f, 0.f, 0.f);
            if (s0 != NNODE) { float4 v = *(const float4*)&base[s0*HD + c];
                acc.x+=v.x; acc.y+=v.y; acc.z+=v.z; acc.w+=v.w; }
            if (s1 != NNODE) { float4 v = *(const float4*)&base[s1*HD + c];
                acc.x+=v.x; acc.y+=v.y; acc.z+=v.z; acc.w+=v.w; }
            if (s2 != NNODE) { float4 v = *(const float4*)&base[s2*HD + c];
                acc.x+=v.x; acc.y+=v.y; acc.z+=v.z; acc.w+=v.w; }
            acc.x*=inv; acc.y*=inv; acc.z*=inv; acc.w*=inv;
            *(float4*)&sv[w*HD + c] = acc;
            *(float4*)&sx[w*HD + c] = acc;
        }
    }
    __syncthreads();

    // 12 SAN GEMM steps with one-chunk-ahead W register prefetch
    const float* Wtab[4] = {Wv, Wo, d1w, d2w};
    const float* btab[4] = {bv, bo, d1b, d2b};
    const float* intab[4]  = {sx, st, sa, st};
    float*       outtab[4] = {st, sa, st, sx};

    for (int j = 0; j < 12; j++) {
        int p = j & 3;
        const float* in = intab[p];
        float* out = outtab[p];
        const float4* wrow = (const float4*)(Wtab[p] + (size_t)tid*HD);
        float acc[8];
        #pragma unroll
        for (int r = 0; r < 8; r++) acc[r] = 0.f;
        float4 wv_[8];
        #pragma unroll
        for (int q = 0; q < 8; q++) wv_[q] = wrow[q];
        #pragma unroll
        for (int kk = 0; kk < 8; kk++) {
            float4 wn_[8];
            if (kk < 7) {
                #pragma unroll
                for (int q = 0; q < 8; q++) wn_[q] = wrow[(kk+1)*8 + q];
            }
            #pragma unroll
            for (int r = 0; r < 8; r++) {
                const float4* ap = (const float4*)(in + r*HD + kk*32);
                #pragma unroll
                for (int q = 0; q < 8; q++) {
                    float4 a = ap[q];
                    acc[r] += a.x*wv_[q].x + a.y*wv_[q].y
                            + a.z*wv_[q].z + a.w*wv_[q].w;
                }
            }
            if (kk < 7) {
                #pragma unroll
                for (int q = 0; q < 8; q++) wv_[q] = wn_[q];
            }
        }
        float bias = btab[p][tid];
        #pragma unroll
        for (int r = 0; r < 8; r++) {
            float v = acc[r] + bias;
            if (p == 2) v = fmaxf(v, 0.f);
            if (p == 3) v += sa[r*HD + tid];
            out[r*HD + tid] = v;
        }
        __syncthreads();
    }

    // W3: s_h = [v_n, x] @ W3^T + b3 (K=512)
    {
        float acc[8];
        #pragma unroll
        for (int r = 0; r < 8; r++) acc[r] = 0.f;
        #pragma unroll
        for (int half = 0; half < 2; half++) {
            const float* in = half ? sx : sv;
            const float4* wrow = (const float4*)(W3w + (size_t)tid*(2*HD)
                                                 + half*HD);
            float4 wv_[8];
            #pragma unroll
            for (int q = 0; q < 8; q++) wv_[q] = wrow[q];
            #pragma unroll
            for (int kk = 0; kk < 8; kk++) {
                float4 wn_[8];
                if (kk < 7) {
                    #pragma unroll
                    for (int q = 0; q < 8; q++) wn_[q] = wrow[(kk+1)*8 + q];
                }
                #pragma unroll
                for (int r = 0; r < 8; r++) {
                    const float4* ap = (const float4*)(in + r*HD + kk*32);
                    #pragma unroll
                    for (int q = 0; q < 8; q++) {
                        float4 a = ap[q];
                        acc[r] += a.x*wv_[q].x + a.y*wv_[q].y
                                + a.z*wv_[q].z + a.w*wv_[q].w;
                    }
                }
                if (kk < 7) {
                    #pragma unroll
                    for (int q = 0; q < 8; q++) wv_[q] = wn_[q];
                }
            }
        }
        float bias = W3b[tid];
        #pragma unroll
        for (int r = 0; r < 8; r++) {
            int gr = b0 + r;
            float v = acc[r] + bias;
            g_sh[gr*HD + tid] = v;
            __nv_bfloat16 h = __float2bfloat16(v);
            __nv_bfloat16 l = __float2bfloat16(v - __bfloat162float(h));
            g_Ah[gr*HD + tid] = h;
            g_Al[gr*HD + tid] = l;
        }
    }
}

// ---------------------------------------------------------------------------
// Scores GEMM (mma.sync bf16, split-fp32). grid (8 m-tiles, 391 n-tiles).
// 8 B-chunks: kc<4 -> B from Bh, MMA with BOTH Ah and Al; kc>=4 -> B from Bl,
// MMA with Ah only. A fragments loaded per-mb to keep live regs < 128.
// ---------------------------------------------------------------------------
__global__ void __launch_bounds__(256, 2)
scores_kernel(float* __restrict__ out) {
    extern __shared__ char smem[];
    uint32_t sb = smem_u32(smem);
    int tid = threadIdx.x, lane = tid & 31, wid = tid >> 5;
    int wm = wid >> 2, wn = wid & 3;
    int m0 = blockIdx.x * 128, n0 = blockIdx.y * 128;
    int q = lane >> 3, r8 = lane & 7;

    uint32_t a_row = (uint32_t)(wm*64 + (q & 1)*8 + r8);
    uint32_t a_kb  = (uint32_t)((q >> 1) * 16);
    uint32_t b_row = (uint32_t)(wn*32 + (q >> 1)*8 + r8);
    uint32_t b_kb  = (uint32_t)((q & 1) * 16);

    float c[4][4][4];
    #pragma unroll
    for (int i = 0; i < 4; i++)
        #pragma unroll
        for (int j = 0; j < 4; j++)
            #pragma unroll
            for (int k = 0; k < 4; k++) c[i][j][k] = 0.f;

    auto load_stage = [&](int kc, int st) {
        bool hiterm = (kc < 4);
        const __nv_bfloat16* Bsrc = hiterm ? g_Bh : g_Bl;
        int k0 = (kc & 3) * KC;
        uint32_t base = sb + st*STAGE3;
        #pragma unroll
        for (int j = tid; j < 1024; j += 256) {
            int row = j >> 3, seg = j & 7;
            uint32_t off = sw128((uint32_t)(row*128 + seg*16));
            int gr = n0 + row; if (gr > VOC-1) gr = VOC-1;
            cp16(base + off, Bsrc + (size_t)gr*HD + k0 + seg*8);
            cp16(base + TILEB + off, g_Ah + (size_t)(m0 + row)*HD + k0 + seg*8);
            if (hiterm)
                cp16(base + 2*TILEB + off,
                     g_Al + (size_t)(m0 + row)*HD + k0 + seg*8);
        }
    };

    load_stage(0, 0);
    CP_COMMIT();

    for (int kc = 0; kc < NCHUNK; kc++) {
        int st = kc & 1;
        if (kc + 1 < NCHUNK) {
            load_stage(kc + 1, st ^ 1);
            CP_COMMIT();
            CP_WAIT(1);
        } else {
            CP_WAIT(0);
        }
        __syncthreads();
        uint32_t base = sb + st*STAGE3;
        bool hiterm = (kc < 4);
        #pragma unroll
        for (int ks = 0; ks < 4; ks++) {
            uint32_t b[4][2];
            #pragma unroll
            for (int nb = 0; nb < 2; nb++) {
                uint32_t r[4];
                ldsm4(r, base + sw128((b_row + nb*16)*128 + b_kb + ks*32));
                b[nb*2+0][0] = r[0]; b[nb*2+0][1] = r[1];
                b[nb*2+1][0] = r[2]; b[nb*2+1][1] = r[3];
            }
            #pragma unroll
            for (int mb = 0; mb < 4; mb++) {
                uint32_t asw = sw128((a_row + mb*16)*128 + a_kb + ks*32);
                uint32_t a[4];
                ldsm4(a, base + TILEB + asw);
                #pragma unroll
                for (int n8 = 0; n8 < 4; n8++)
                    mma16816(c[mb][n8], a, b[n8]);
                if (hiterm) {
                    uint32_t al[4];
                    ldsm4(al, base + 2*TILEB + asw);
                    #pragma unroll
                    for (int n8 = 0; n8 < 4; n8++)
                        mma16816(c[mb][n8], al, b[n8]);
                }
            }
        }
        __syncthreads();
    }

    #pragma unroll
    for (int mb = 0; mb < 4; mb++) {
        int gr0 = m0 + wm*64 + mb*16 + (lane >> 2);
        #pragma unroll
        for (int n8 = 0; n8 < 4; n8++) {
            int col = n0 + wn*32 + n8*8 + (lane & 3)*2;
            if (col < VOC) {
                *(float2*)&out[(size_t)gr0*VOC + col]     =
                    make_float2(c[mb][n8][0], c[mb][n8][1]);
                *(float2*)&out[(size_t)(gr0+8)*VOC + col] =
                    make_float2(c[mb][n8][2], c[mb][n8][3]);
            }
        }
    }
}

// ---------------------------------------------------------------------------
// y_hat[b] = dot(s_h[b], emb_weight[cue[b]])  (exact fp32 path)
// ---------------------------------------------------------------------------
__global__ void yhat_kernel(const float* __restrict__ emb,
                            const int*   __restrict__ cue,
                            float* __restrict__ out) {
    int b = blockIdx.x, tid = threadIdx.x;
    float v = g_sh[b*HD + tid] * emb[((size_t)cue[b])*HD + tid];
    #pragma unroll
    for (int o = 16; o > 0; o >>= 1) v += __shfl_down_sync(0xffffffffu, v, o);
    __shared__ float red[8];
    if ((tid & 31) == 0) red[tid >> 5] = v;
    __syncthreads();
    if (tid == 0) {
        float s = 0.f;
        #pragma unroll
        for (int i = 0; i < 8; i++) s += red[i];
        out[b] = s;
    }
}

// ---------------------------------------------------------------------------
static bool g_init = false;

static void resolve_once() {
    if (g_init) return;
    cudaFuncSetAttribute(scores_kernel,
                         cudaFuncAttributeMaxDynamicSharedMemorySize, SMEM_SZ);
    g_init = true;
}

extern "C" void kernel_launch(void* const* d_in, const int* in_sizes, int n_in,
                              void* d_out, int out_size) {
    const float* node_embedding = (const float*)d_in[0];
    const float* emb_weight     = (const float*)d_in[1];
    const float* itemset_len    = (const float*)d_in[2];
    const float* in_proj_w      = (const float*)d_in[3];
    const float* in_proj_b      = (const float*)d_in[4];
    const float* out_proj_w     = (const float*)d_in[5];
    const float* out_proj_b     = (const float*)d_in[6];
    const float* d1_w           = (const float*)d_in[7];
    const float* d1_b           = (const float*)d_in[8];
    const float* d2_w           = (const float*)d_in[9];
    const float* d2_b           = (const float*)d_in[10];
    const float* W3_w           = (const float*)d_in[11];
    const float* W3_b           = (const float*)d_in[12];
    const int*   sequence       = (const int*)d_in[14];
    const int*   cue            = (const int*)d_in[16];

    resolve_once();

    // Chain + B-side split fused in ONE launch (independent halves overlap)
    prep_kernel<<<CHAIN_CTAS + CONV_CTAS, 256>>>(
        node_embedding, itemset_len, sequence, emb_weight,
        in_proj_w + 2*HD*HD, in_proj_b + 2*HD,
        out_proj_w, out_proj_b,
        d1_w, d1_b, d2_w, d2_b, W3_w, W3_b);

    // Outputs
    float* out = (float*)d_out;
    scores_kernel<<<dim3(8, (VOC + 127)/128), 256, SMEM_SZ>>>(out + BSESS);
    yhat_kernel<<<BSESS, HD>>>(emb_weight, cue, out);
}

// round 10
// speedup vs baseline: 1.6644x; 1.6644x over previous
#include <cuda_runtime.h>
#include <cuda_bf16.h>
#include <cstdint>

// Problem constants
#define BSESS 1024
#define NNODE 32
#define SLEN  50
#define HD    256
#define VOC   50000

// Scores GEMM config: C[1024,50000] split-bf16.
#define KC      64
#define NCHUNK  8
#define TILEB   16384              // 128 rows x 128 B
#define STAGE3  (3*TILEB)          // B + Ah + Al = 48 KB
#define SMEM_SZ (2*STAGE3)         // 96 KB double buffered

#define W3OFF   262144             // float offset of W3^T inside g_Wt

// Scratch
__device__ float g_sh[BSESS*HD];
__device__ float g_Wt[4*HD*HD + 2*HD*HD];   // 4 SAN mats + W3 (512x256)
__device__ __nv_bfloat16 g_Bh[(size_t)VOC*HD];
__device__ __nv_bfloat16 g_Bl[(size_t)VOC*HD];
__device__ __nv_bfloat16 g_Ah[BSESS*HD];
__device__ __nv_bfloat16 g_Al[BSESS*HD];

// ---------------------------------------------------------------------------
// Helpers (baseline ISA only)
// ---------------------------------------------------------------------------
__device__ __forceinline__ uint32_t smem_u32(const void* p) {
    uint32_t a;
    asm("{ .reg .u64 t; cvta.to.shared.u64 t, %1; cvt.u32.u64 %0, t; }"
        : "=r"(a) : "l"(p));
    return a;
}
__device__ __forceinline__ void cp16(uint32_t dst, const void* src) {
    asm volatile("cp.async.cg.shared.global [%0], [%1], 16;"
                 :: "r"(dst), "l"(src));
}
#define CP_COMMIT() asm volatile("cp.async.commit_group;" ::: "memory")
#define CP_WAIT(n)  asm volatile("cp.async.wait_group %0;" :: "n"(n) : "memory")

__device__ __forceinline__ uint32_t sw128(uint32_t x) {
    return x ^ ((x >> 3) & 0x70);
}
__device__ __forceinline__ void ldsm4(uint32_t* r, uint32_t addr) {
    asm volatile("ldmatrix.sync.aligned.m8n8.x4.shared.b16 {%0,%1,%2,%3}, [%4];"
                 : "=r"(r[0]), "=r"(r[1]), "=r"(r[2]), "=r"(r[3]) : "r"(addr));
}
__device__ __forceinline__ void mma16816(float* c, const uint32_t* a,
                                         const uint32_t* b) {
    asm volatile(
        "mma.sync.aligned.m16n8k16.row.col.f32.bf16.bf16.f32 "
        "{%0,%1,%2,%3}, {%4,%5,%6,%7}, {%8,%9}, {%0,%1,%2,%3};"
        : "+f"(c[0]), "+f"(c[1]), "+f"(c[2]), "+f"(c[3])
        : "r"(a[0]), "r"(a[1]), "r"(a[2]), "r"(a[3]), "r"(b[0]), "r"(b[1]));
}

// ---------------------------------------------------------------------------
// One-time weight transpose into packed [k][col] layout:
//   g_Wt[base + (k>>2)*1024 + col*4 + (k&3)] = W[col][k]
// so a warp's 32 lanes read consecutive 16B chunks (4 lines per LDG.128,
// not 32). Reads are fully coalesced; writes are scattered but tiny (1.5 MB).
// ---------------------------------------------------------------------------
__global__ void transpose_w(const float* __restrict__ Wv,
                            const float* __restrict__ Wo,
                            const float* __restrict__ d1w,
                            const float* __restrict__ d2w,
                            const float* __restrict__ W3w) {
    int m = blockIdx.z;
    int kt = blockIdx.x*32, ct = blockIdx.y*32;
    const float* src; float* dst; int KD;
    if (m < 4) {
        if (kt >= 256) return;
        KD = 256; dst = g_Wt + m*65536;
        src = (m==0) ? Wv : (m==1) ? Wo : (m==2) ? d1w : d2w;
    } else {
        KD = 512; dst = g_Wt + W3OFF; src = W3w;
    }
    int x = threadIdx.x & 31, y8 = threadIdx.x >> 5;
    int k = kt + x;
    for (int i = y8; i < 32; i += 8) {
        int col = ct + i;
        dst[((k >> 2) << 10) + col*4 + (k & 3)] = src[(size_t)col*KD + k];
    }
}

// ---------------------------------------------------------------------------
// Fused chain kernel: vn gather -> 3x SAN blocks -> W3 -> s_h + A bf16 split.
// 128 CTAs x 8 rows. Weights read from g_Wt (coalesced), register
// double-buffered one 32-k chunk ahead. No intra-step barriers.
// ---------------------------------------------------------------------------
__global__ void __launch_bounds__(256, 1)
chain_kernel(const float* __restrict__ node_emb,
             const float* __restrict__ itemset_len,
             const int*   __restrict__ sequence,
             const float* __restrict__ bv,  const float* __restrict__ bo,
             const float* __restrict__ d1b, const float* __restrict__ d2b,
             const float* __restrict__ W3b) {
    __shared__ float sv[8*HD];
    __shared__ float sx[8*HD];
    __shared__ float sa[8*HD];
    __shared__ float st[8*HD];
    int tid = threadIdx.x, w = tid >> 5, lane = tid & 31;
    int b0 = blockIdx.x * 8;

    // v_n gather: warp w -> row w
    {
        int b = b0 + w;
        int t = b*SLEN + (SLEN-1);
        int s0 = sequence[t*3+0], s1 = sequence[t*3+1], s2 = sequence[t*3+2];
        float inv = 1.f / itemset_len[t];
        const float* base = node_emb + (size_t)b*NNODE*HD;
        #pragma unroll
        for (int p = 0; p < 2; p++) {
            int c = lane*8 + p*4;
            float4 acc = make_float4(0.f, 0.f, 0.f, 0.f);
            if (s0 != NNODE) { float4 v = *(const float4*)&base[s0*HD + c];
                acc.x+=v.x; acc.y+=v.y; acc.z+=v.z; acc.w+=v.w; }
            if (s1 != NNODE) { float4 v = *(const float4*)&base[s1*HD + c];
                acc.x+=v.x; acc.y+=v.y; acc.z+=v.z; acc.w+=v.w; }
            if (s2 != NNODE) { float4 v = *(const float4*)&base[s2*HD + c];
                acc.x+=v.x; acc.y+=v.y; acc.z+=v.z; acc.w+=v.w; }
            acc.x*=inv; acc.y*=inv; acc.z*=inv; acc.w*=inv;
            *(float4*)&sv[w*HD + c] = acc;
            *(float4*)&sx[w*HD + c] = acc;
        }
    }
    __syncthreads();

    const float* btab[4] = {bv, bo, d1b, d2b};
    const float* intab[4]  = {sx, st, sa, st};
    float*       outtab[4] = {st, sa, st, sx};

    for (int j = 0; j <= 12; j++) {
        bool w3 = (j == 12);
        int p = j & 3;
        const float* wt = w3 ? (g_Wt + W3OFF) : (g_Wt + p*65536);
        int nc = w3 ? 16 : 8;
        const float* in_s = intab[p];
        float* out_s = outtab[p];

        float acc[8];
        #pragma unroll
        for (int r = 0; r < 8; r++) acc[r] = 0.f;

        float4 wc[8], wn[8];
        #pragma unroll
        for (int q = 0; q < 8; q++)
            wc[q] = *(const float4*)&wt[(size_t)q*1024 + tid*4];

        for (int c = 0; c < nc; c++) {
            if (c + 1 < nc) {
                #pragma unroll
                for (int q = 0; q < 8; q++)
                    wn[q] = *(const float4*)&wt[(size_t)((c+1)*8 + q)*1024
                                                + tid*4];
            }
            const float* in = w3 ? ((c < 8) ? sv : sx) : in_s;
            int l0 = (c & 7)*32;
            #pragma unroll
            for (int q = 0; q < 8; q++) {
                #pragma unroll
                for (int r = 0; r < 8; r++) {
                    float4 a = *(const float4*)&in[r*HD + l0 + q*4];
                    acc[r] += a.x*wc[q].x + a.y*wc[q].y
                            + a.z*wc[q].z + a.w*wc[q].w;
                }
            }
            if (c + 1 < nc) {
                #pragma unroll
                for (int q = 0; q < 8; q++) wc[q] = wn[q];
            }
        }

        if (!w3) {
            float bias = btab[p][tid];
            #pragma unroll
            for (int r = 0; r < 8; r++) {
                float v = acc[r] + bias;
                if (p == 2) v = fmaxf(v, 0.f);
                if (p == 3) v += sa[r*HD + tid];
                out_s[r*HD + tid] = v;
            }
            __syncthreads();
        } else {
            float bias = W3b[tid];
            #pragma unroll
            for (int r = 0; r < 8; r++) {
                int gr = b0 + r;
                float v = acc[r] + bias;
                g_sh[gr*HD + tid] = v;
                __nv_bfloat16 h = __float2bfloat16(v);
                __nv_bfloat16 l = __float2bfloat16(v - __bfloat162float(h));
                g_Ah[gr*HD + tid] = h;
                g_Al[gr*HD + tid] = l;
            }
        }
    }
}

// ---------------------------------------------------------------------------
// fp32 -> (bf16 hi, bf16 lo) split (B side)
// ---------------------------------------------------------------------------
__global__ void conv_split(const float* __restrict__ src,
                           __nv_bfloat16* __restrict__ hi,
                           __nv_bfloat16* __restrict__ lo, int n4) {
    int i = blockIdx.x*256 + threadIdx.x;
    if (i >= n4) return;
    float4 v = ((const float4*)src)[i];
    __nv_bfloat16 h0 = __float2bfloat16(v.x), h1 = __float2bfloat16(v.y),
                  h2 = __float2bfloat16(v.z), h3 = __float2bfloat16(v.w);
    __nv_bfloat16 l0 = __float2bfloat16(v.x - __bfloat162float(h0));
    __nv_bfloat16 l1 = __float2bfloat16(v.y - __bfloat162float(h1));
    __nv_bfloat16 l2 = __float2bfloat16(v.z - __bfloat162float(h2));
    __nv_bfloat16 l3 = __float2bfloat16(v.w - __bfloat162float(h3));
    ((__nv_bfloat162*)hi)[i*2+0] = __nv_bfloat162(h0, h1);
    ((__nv_bfloat162*)hi)[i*2+1] = __nv_bfloat162(h2, h3);
    ((__nv_bfloat162*)lo)[i*2+0] = __nv_bfloat162(l0, l1);
    ((__nv_bfloat162*)lo)[i*2+1] = __nv_bfloat162(l2, l3);
}

// ---------------------------------------------------------------------------
// Scores GEMM (mma.sync bf16, split-fp32). grid (8 m-tiles, 391 n-tiles).
// 8 B-chunks: kc<4 -> Bh (MMA with Ah AND Al), kc>=4 -> Bl (Ah only).
// ---------------------------------------------------------------------------
__global__ void __launch_bounds__(256, 2)
scores_kernel(float* __restrict__ out) {
    extern __shared__ char smem[];
    uint32_t sb = smem_u32(smem);
    int tid = threadIdx.x, lane = tid & 31, wid = tid >> 5;
    int wm = wid >> 2, wn = wid & 3;
    int m0 = blockIdx.x * 128, n0 = blockIdx.y * 128;
    int q = lane >> 3, r8 = lane & 7;

    uint32_t a_row = (uint32_t)(wm*64 + (q & 1)*8 + r8);
    uint32_t a_kb  = (uint32_t)((q >> 1) * 16);
    uint32_t b_row = (uint32_t)(wn*32 + (q >> 1)*8 + r8);
    uint32_t b_kb  = (uint32_t)((q & 1) * 16);

    float c[4][4][4];
    #pragma unroll
    for (int i = 0; i < 4; i++)
        #pragma unroll
        for (int j = 0; j < 4; j++)
            #pragma unroll
            for (int k = 0; k < 4; k++) c[i][j][k] = 0.f;

    auto load_stage = [&](int kc, int st) {
        bool hiterm = (kc < 4);
        const __nv_bfloat16* Bsrc = hiterm ? g_Bh : g_Bl;
        int k0 = (kc & 3) * KC;
        uint32_t base = sb + st*STAGE3;
        #pragma unroll
        for (int j = tid; j < 1024; j += 256) {
            int row = j >> 3, seg = j & 7;
            uint32_t off = sw128((uint32_t)(row*128 + seg*16));
            int gr = n0 + row; if (gr > VOC-1) gr = VOC-1;
            cp16(base + off, Bsrc + (size_t)gr*HD + k0 + seg*8);
            cp16(base + TILEB + off, g_Ah + (size_t)(m0 + row)*HD + k0 + seg*8);
            if (hiterm)
                cp16(base + 2*TILEB + off,
                     g_Al + (size_t)(m0 + row)*HD + k0 + seg*8);
        }
    };

    load_stage(0, 0);
    CP_COMMIT();

    for (int kc = 0; kc < NCHUNK; kc++) {
        int st = kc & 1;
        if (kc + 1 < NCHUNK) {
            load_stage(kc + 1, st ^ 1);
            CP_COMMIT();
            CP_WAIT(1);
        } else {
            CP_WAIT(0);
        }
        __syncthreads();
        uint32_t base = sb + st*STAGE3;
        bool hiterm = (kc < 4);
        #pragma unroll
        for (int ks = 0; ks < 4; ks++) {
            uint32_t b[4][2];
            #pragma unroll
            for (int nb = 0; nb < 2; nb++) {
                uint32_t r[4];
                ldsm4(r, base + sw128((b_row + nb*16)*128 + b_kb + ks*32));
                b[nb*2+0][0] = r[0]; b[nb*2+0][1] = r[1];
                b[nb*2+1][0] = r[2]; b[nb*2+1][1] = r[3];
            }
            #pragma unroll
            for (int mb = 0; mb < 4; mb++) {
                uint32_t asw = sw128((a_row + mb*16)*128 + a_kb + ks*32);
                uint32_t a[4];
                ldsm4(a, base + TILEB + asw);
                #pragma unroll
                for (int n8 = 0; n8 < 4; n8++)
                    mma16816(c[mb][n8], a, b[n8]);
                if (hiterm) {
                    uint32_t al[4];
                    ldsm4(al, base + 2*TILEB + asw);
                    #pragma unroll
                    for (int n8 = 0; n8 < 4; n8++)
                        mma16816(c[mb][n8], al, b[n8]);
                }
            }
        }
        __syncthreads();
    }

    #pragma unroll
    for (int mb = 0; mb < 4; mb++) {
        int gr0 = m0 + wm*64 + mb*16 + (lane >> 2);
        #pragma unroll
        for (int n8 = 0; n8 < 4; n8++) {
            int col = n0 + wn*32 + n8*8 + (lane & 3)*2;
            if (col < VOC) {
                *(float2*)&out[(size_t)gr0*VOC + col]     =
                    make_float2(c[mb][n8][0], c[mb][n8][1]);
                *(float2*)&out[(size_t)(gr0+8)*VOC + col] =
                    make_float2(c[mb][n8][2], c[mb][n8][3]);
            }
        }
    }
}

// ---------------------------------------------------------------------------
// y_hat[b] = dot(s_h[b], emb_weight[cue[b]])  (exact fp32 path)
// ---------------------------------------------------------------------------
__global__ void yhat_kernel(const float* __restrict__ emb,
                            const int*   __restrict__ cue,
                            float* __restrict__ out) {
    int b = blockIdx.x, tid = threadIdx.x;
    float v = g_sh[b*HD + tid] * emb[((size_t)cue[b])*HD + tid];
    #pragma unroll
    for (int o = 16; o > 0; o >>= 1) v += __shfl_down_sync(0xffffffffu, v, o);
    __shared__ float red[8];
    if ((tid & 31) == 0) red[tid >> 5] = v;
    __syncthreads();
    if (tid == 0) {
        float s = 0.f;
        #pragma unroll
        for (int i = 0; i < 8; i++) s += red[i];
        out[b] = s;
    }
}

// ---------------------------------------------------------------------------
static __nv_bfloat16 *pBh, *pBl;
static bool g_init = false;

static void resolve_once() {
    if (g_init) return;
    cudaGetSymbolAddress((void**)&pBh, g_Bh);
    cudaGetSymbolAddress((void**)&pBl, g_Bl);
    cudaFuncSetAttribute(scores_kernel,
                         cudaFuncAttributeMaxDynamicSharedMemorySize, SMEM_SZ);
    g_init = true;
}

extern "C" void kernel_launch(void* const* d_in, const int* in_sizes, int n_in,
                              void* d_out, int out_size) {
    const float* node_embedding = (const float*)d_in[0];
    const float* emb_weight     = (const float*)d_in[1];
    const float* itemset_len    = (const float*)d_in[2];
    const float* in_proj_w      = (const float*)d_in[3];
    const float* in_proj_b      = (const float*)d_in[4];
    const float* out_proj_w     = (const float*)d_in[5];
    const float* out_proj_b     = (const float*)d_in[6];
    const float* d1_w           = (const float*)d_in[7];
    const float* d1_b           = (const float*)d_in[8];
    const float* d2_w           = (const float*)d_in[9];
    const float* d2_b           = (const float*)d_in[10];
    const float* W3_w           = (const float*)d_in[11];
    const float* W3_b           = (const float*)d_in[12];
    const int*   sequence       = (const int*)d_in[14];
    const int*   cue            = (const int*)d_in[16];

    resolve_once();

    // One-time weight transpose (tiny)
    transpose_w<<<dim3(16, 8, 5), 256>>>(in_proj_w + 2*HD*HD, out_proj_w,
                                         d1_w, d2_w, W3_w);

    // B-side split
    conv_split<<<(VOC*HD/4 + 255)/256, 256>>>(emb_weight, pBh, pBl, VOC*HD/4);

    // SAN chain + W3 + A-side split, one launch, coalesced weight reads
    chain_kernel<<<BSESS/8, 256>>>(node_embedding, itemset_len, sequence,
                                   in_proj_b + 2*HD, out_proj_b,
                                   d1_b, d2_b, W3_b);

    // Outputs
    float* out = (float*)d_out;
    scores_kernel<<<dim3(8, (VOC + 127)/128), 256, SMEM_SZ>>>(out + BSESS);
    yhat_kernel<<<BSESS, HD>>>(emb_weight, cue, out);
}

// round 11
// speedup vs baseline: 1.6810x; 1.0100x over previous
#include <cuda_runtime.h>
#include <cuda_bf16.h>
#include <cstdint>

// Problem constants
#define BSESS 1024
#define NNODE 32
#define SLEN  50
#define HD    256
#define VOC   50000

// Scores GEMM config: C[1024,50000] split-bf16.
#define KC      64
#define NCHUNK  8
#define TILEB   16384              // 128 rows x 128 B
#define STAGE3  (3*TILEB)          // B + Ah + Al = 48 KB
#define SMEM_SZ (2*STAGE3)         // 96 KB double buffered

#define W3OFF   262144             // float offset of W3^T inside g_Wt

// Scratch
__device__ float g_sh[BSESS*HD];
__device__ float g_Wt[4*HD*HD + 2*HD*HD];   // 4 SAN mats + W3 (512x256)
__device__ __nv_bfloat16 g_Bh[(size_t)VOC*HD];
__device__ __nv_bfloat16 g_Bl[(size_t)VOC*HD];
__device__ __nv_bfloat16 g_Ah[BSESS*HD];
__device__ __nv_bfloat16 g_Al[BSESS*HD];

// ---------------------------------------------------------------------------
// Helpers (baseline ISA only)
// ---------------------------------------------------------------------------
__device__ __forceinline__ uint32_t smem_u32(const void* p) {
    uint32_t a;
    asm("{ .reg .u64 t; cvta.to.shared.u64 t, %1; cvt.u32.u64 %0, t; }"
        : "=r"(a) : "l"(p));
    return a;
}
__device__ __forceinline__ void cp16(uint32_t dst, const void* src) {
    asm volatile("cp.async.cg.shared.global [%0], [%1], 16;"
                 :: "r"(dst), "l"(src));
}
#define CP_COMMIT() asm volatile("cp.async.commit_group;" ::: "memory")
#define CP_WAIT(n)  asm volatile("cp.async.wait_group %0;" :: "n"(n) : "memory")

__device__ __forceinline__ uint32_t sw128(uint32_t x) {
    return x ^ ((x >> 3) & 0x70);
}
__device__ __forceinline__ void ldsm4(uint32_t* r, uint32_t addr) {
    asm volatile("ldmatrix.sync.aligned.m8n8.x4.shared.b16 {%0,%1,%2,%3}, [%4];"
                 : "=r"(r[0]), "=r"(r[1]), "=r"(r[2]), "=r"(r[3]) : "r"(addr));
}
__device__ __forceinline__ void mma16816(float* c, const uint32_t* a,
                                         const uint32_t* b) {
    asm volatile(
        "mma.sync.aligned.m16n8k16.row.col.f32.bf16.bf16.f32 "
        "{%0,%1,%2,%3}, {%4,%5,%6,%7}, {%8,%9}, {%0,%1,%2,%3};"
        : "+f"(c[0]), "+f"(c[1]), "+f"(c[2]), "+f"(c[3])
        : "r"(a[0]), "r"(a[1]), "r"(a[2]), "r"(a[3]), "r"(b[0]), "r"(b[1]));
}

// ---------------------------------------------------------------------------
// One-time weight transpose into packed [k][col] layout:
//   g_Wt[base + (k>>2)*1024 + col*4 + (k&3)] = W[col][k]
// ---------------------------------------------------------------------------
__global__ void transpose_w(const float* __restrict__ Wv,
                            const float* __restrict__ Wo,
                            const float* __restrict__ d1w,
                            const float* __restrict__ d2w,
                            const float* __restrict__ W3w) {
    int m = blockIdx.z;
    int kt = blockIdx.x*32, ct = blockIdx.y*32;
    const float* src; float* dst; int KD;
    if (m < 4) {
        if (kt >= 256) return;
        KD = 256; dst = g_Wt + m*65536;
        src = (m==0) ? Wv : (m==1) ? Wo : (m==2) ? d1w : d2w;
    } else {
        KD = 512; dst = g_Wt + W3OFF; src = W3w;
    }
    int x = threadIdx.x & 31, y8 = threadIdx.x >> 5;
    int k = kt + x;
    for (int i = y8; i < 32; i += 8) {
        int col = ct + i;
        dst[((k >> 2) << 10) + col*4 + (k & 3)] = src[(size_t)col*KD + k];
    }
}

// ---------------------------------------------------------------------------
// Fused chain kernel: vn gather -> 3x SAN blocks -> W3 -> s_h + A bf16 split.
// 128 CTAs x 8 rows. Weights read from g_Wt (coalesced), register
// double-buffered one 32-k chunk ahead.
// ---------------------------------------------------------------------------
__global__ void __launch_bounds__(256, 1)
chain_kernel(const float* __restrict__ node_emb,
             const float* __restrict__ itemset_len,
             const int*   __restrict__ sequence,
             const float* __restrict__ bv,  const float* __restrict__ bo,
             const float* __restrict__ d1b, const float* __restrict__ d2b,
             const float* __restrict__ W3b) {
    __shared__ float sv[8*HD];
    __shared__ float sx[8*HD];
    __shared__ float sa[8*HD];
    __shared__ float st[8*HD];
    int tid = threadIdx.x, w = tid >> 5, lane = tid & 31;
    int b0 = blockIdx.x * 8;

    // v_n gather: warp w -> row w
    {
        int b = b0 + w;
        int t = b*SLEN + (SLEN-1);
        int s0 = sequence[t*3+0], s1 = sequence[t*3+1], s2 = sequence[t*3+2];
        float inv = 1.f / itemset_len[t];
        const float* base = node_emb + (size_t)b*NNODE*HD;
        #pragma unroll
        for (int p = 0; p < 2; p++) {
            int c = lane*8 + p*4;
            float4 acc = make_float4(0.f, 0.f, 0.f, 0.f);
            if (s0 != NNODE) { float4 v = *(const float4*)&base[s0*HD + c];
                acc.x+=v.x; acc.y+=v.y; acc.z+=v.z; acc.w+=v.w; }
            if (s1 != NNODE) { float4 v = *(const float4*)&base[s1*HD + c];
                acc.x+=v.x; acc.y+=v.y; acc.z+=v.z; acc.w+=v.w; }
            if (s2 != NNODE) { float4 v = *(const float4*)&base[s2*HD + c];
                acc.x+=v.x; acc.y+=v.y; acc.z+=v.z; acc.w+=v.w; }
            acc.x*=inv; acc.y*=inv; acc.z*=inv; acc.w*=inv;
            *(float4*)&sv[w*HD + c] = acc;
            *(float4*)&sx[w*HD + c] = acc;
        }
    }
    __syncthreads();

    const float* btab[4] = {bv, bo, d1b, d2b};
    const float* intab[4]  = {sx, st, sa, st};
    float*       outtab[4] = {st, sa, st, sx};

    for (int j = 0; j <= 12; j++) {
        bool w3 = (j == 12);
        int p = j & 3;
        const float* wt = w3 ? (g_Wt + W3OFF) : (g_Wt + p*65536);
        int nc = w3 ? 16 : 8;
        const float* in_s = intab[p];
        float* out_s = outtab[p];

        float acc[8];
        #pragma unroll
        for (int r = 0; r < 8; r++) acc[r] = 0.f;

        float4 wc[8], wn[8];
        #pragma unroll
        for (int q = 0; q < 8; q++)
            wc[q] = *(const float4*)&wt[(size_t)q*1024 + tid*4];

        for (int c = 0; c < nc; c++) {
            if (c + 1 < nc) {
                #pragma unroll
                for (int q = 0; q < 8; q++)
                    wn[q] = *(const float4*)&wt[(size_t)((c+1)*8 + q)*1024
                                                + tid*4];
            }
            const float* in = w3 ? ((c < 8) ? sv : sx) : in_s;
            int l0 = (c & 7)*32;
            #pragma unroll
            for (int q = 0; q < 8; q++) {
                #pragma unroll
                for (int r = 0; r < 8; r++) {
                    float4 a = *(const float4*)&in[r*HD + l0 + q*4];
                    acc[r] += a.x*wc[q].x + a.y*wc[q].y
                            + a.z*wc[q].z + a.w*wc[q].w;
                }
            }
            if (c + 1 < nc) {
                #pragma unroll
                for (int q = 0; q < 8; q++) wc[q] = wn[q];
            }
        }

        if (!w3) {
            float bias = btab[p][tid];
            #pragma unroll
            for (int r = 0; r < 8; r++) {
                float v = acc[r] + bias;
                if (p == 2) v = fmaxf(v, 0.f);
                if (p == 3) v += sa[r*HD + tid];
                out_s[r*HD + tid] = v;
            }
            __syncthreads();
        } else {
            float bias = W3b[tid];
            #pragma unroll
            for (int r = 0; r < 8; r++) {
                int gr = b0 + r;
                float v = acc[r] + bias;
                g_sh[gr*HD + tid] = v;
                __nv_bfloat16 h = __float2bfloat16(v);
                __nv_bfloat16 l = __float2bfloat16(v - __bfloat162float(h));
                g_Ah[gr*HD + tid] = h;
                g_Al[gr*HD + tid] = l;
            }
        }
    }
}

// ---------------------------------------------------------------------------
// fp32 -> (bf16 hi, bf16 lo) split (B side)
// ---------------------------------------------------------------------------
__global__ void conv_split(const float* __restrict__ src,
                           __nv_bfloat16* __restrict__ hi,
                           __nv_bfloat16* __restrict__ lo, int n4) {
    int i = blockIdx.x*256 + threadIdx.x;
    if (i >= n4) return;
    float4 v = ((const float4*)src)[i];
    __nv_bfloat16 h0 = __float2bfloat16(v.x), h1 = __float2bfloat16(v.y),
                  h2 = __float2bfloat16(v.z), h3 = __float2bfloat16(v.w);
    __nv_bfloat16 l0 = __float2bfloat16(v.x - __bfloat162float(h0));
    __nv_bfloat16 l1 = __float2bfloat16(v.y - __bfloat162float(h1));
    __nv_bfloat16 l2 = __float2bfloat16(v.z - __bfloat162float(h2));
    __nv_bfloat16 l3 = __float2bfloat16(v.w - __bfloat162float(h3));
    ((__nv_bfloat162*)hi)[i*2+0] = __nv_bfloat162(h0, h1);
    ((__nv_bfloat162*)hi)[i*2+1] = __nv_bfloat162(h2, h3);
    ((__nv_bfloat162*)lo)[i*2+0] = __nv_bfloat162(l0, l1);
    ((__nv_bfloat162*)lo)[i*2+1] = __nv_bfloat162(l2, l3);
}

// ---------------------------------------------------------------------------
// Scores GEMM (mma.sync bf16, split-fp32). grid (8 m-tiles, 391 n-tiles).
// 8 B-chunks: kc<4 -> Bh (MMA with Ah AND Al), kc>=4 -> Bl (Ah only).
// ---------------------------------------------------------------------------
__global__ void __launch_bounds__(256, 2)
scores_kernel(float* __restrict__ out) {
    extern __shared__ char smem[];
    uint32_t sb = smem_u32(smem);
    int tid = threadIdx.x, lane = tid & 31, wid = tid >> 5;
    int wm = wid >> 2, wn = wid & 3;
    int m0 = blockIdx.x * 128, n0 = blockIdx.y * 128;
    int q = lane >> 3, r8 = lane & 7;

    uint32_t a_row = (uint32_t)(wm*64 + (q & 1)*8 + r8);
    uint32_t a_kb  = (uint32_t)((q >> 1) * 16);
    uint32_t b_row = (uint32_t)(wn*32 + (q >> 1)*8 + r8);
    uint32_t b_kb  = (uint32_t)((q & 1) * 16);

    float c[4][4][4];
    #pragma unroll
    for (int i = 0; i < 4; i++)
        #pragma unroll
        for (int j = 0; j < 4; j++)
            #pragma unroll
            for (int k = 0; k < 4; k++) c[i][j][k] = 0.f;

    auto load_stage = [&](int kc, int st) {
        bool hiterm = (kc < 4);
        const __nv_bfloat16* Bsrc = hiterm ? g_Bh : g_Bl;
        int k0 = (kc & 3) * KC;
        uint32_t base = sb + st*STAGE3;
        #pragma unroll
        for (int j = tid; j < 1024; j += 256) {
            int row = j >> 3, seg = j & 7;
            uint32_t off = sw128((uint32_t)(row*128 + seg*16));
            int gr = n0 + row; if (gr > VOC-1) gr = VOC-1;
            cp16(base + off, Bsrc + (size_t)gr*HD + k0 + seg*8);
            cp16(base + TILEB + off, g_Ah + (size_t)(m0 + row)*HD + k0 + seg*8);
            if (hiterm)
                cp16(base + 2*TILEB + off,
                     g_Al + (size_t)(m0 + row)*HD + k0 + seg*8);
        }
    };

    load_stage(0, 0);
    CP_COMMIT();

    for (int kc = 0; kc < NCHUNK; kc++) {
        int st = kc & 1;
        if (kc + 1 < NCHUNK) {
            load_stage(kc + 1, st ^ 1);
            CP_COMMIT();
            CP_WAIT(1);
        } else {
            CP_WAIT(0);
        }
        __syncthreads();
        uint32_t base = sb + st*STAGE3;
        bool hiterm = (kc < 4);
        #pragma unroll
        for (int ks = 0; ks < 4; ks++) {
            uint32_t b[4][2];
            #pragma unroll
            for (int nb = 0; nb < 2; nb++) {
                uint32_t r[4];
                ldsm4(r, base + sw128((b_row + nb*16)*128 + b_kb + ks*32));
                b[nb*2+0][0] = r[0]; b[nb*2+0][1] = r[1];
                b[nb*2+1][0] = r[2]; b[nb*2+1][1] = r[3];
            }
            #pragma unroll
            for (int mb = 0; mb < 4; mb++) {
                uint32_t asw = sw128((a_row + mb*16)*128 + a_kb + ks*32);
                uint32_t a[4];
                ldsm4(a, base + TILEB + asw);
                #pragma unroll
                for (int n8 = 0; n8 < 4; n8++)
                    mma16816(c[mb][n8], a, b[n8]);
                if (hiterm) {
                    uint32_t al[4];
                    ldsm4(al, base + 2*TILEB + asw);
                    #pragma unroll
                    for (int n8 = 0; n8 < 4; n8++)
                        mma16816(c[mb][n8], al, b[n8]);
                }
            }
        }
        __syncthreads();
    }

    #pragma unroll
    for (int mb = 0; mb < 4; mb++) {
        int gr0 = m0 + wm*64 + mb*16 + (lane >> 2);
        #pragma unroll
        for (int n8 = 0; n8 < 4; n8++) {
            int col = n0 + wn*32 + n8*8 + (lane & 3)*2;
            if (col < VOC) {
                *(float2*)&out[(size_t)gr0*VOC + col]     =
                    make_float2(c[mb][n8][0], c[mb][n8][1]);
                *(float2*)&out[(size_t)(gr0+8)*VOC + col] =
                    make_float2(c[mb][n8][2], c[mb][n8][3]);
            }
        }
    }
}

// ---------------------------------------------------------------------------
// y_hat[b] = dot(s_h[b], emb_weight[cue[b]])  (exact fp32 path)
// ---------------------------------------------------------------------------
__global__ void yhat_kernel(const float* __restrict__ emb,
                            const int*   __restrict__ cue,
                            float* __restrict__ out) {
    int b = blockIdx.x, tid = threadIdx.x;
    float v = g_sh[b*HD + tid] * emb[((size_t)cue[b])*HD + tid];
    #pragma unroll
    for (int o = 16; o > 0; o >>= 1) v += __shfl_down_sync(0xffffffffu, v, o);
    __shared__ float red[8];
    if ((tid & 31) == 0) red[tid >> 5] = v;
    __syncthreads();
    if (tid == 0) {
        float s = 0.f;
        #pragma unroll
        for (int i = 0; i < 8; i++) s += red[i];
        out[b] = s;
    }
}

// ---------------------------------------------------------------------------
static __nv_bfloat16 *pBh, *pBl;
static cudaStream_t sB = nullptr;
static cudaEvent_t evFork = nullptr, evJoin = nullptr;
static bool g_init = false;

static void resolve_once() {
    if (g_init) return;
    cudaGetSymbolAddress((void**)&pBh, g_Bh);
    cudaGetSymbolAddress((void**)&pBl, g_Bl);
    cudaFuncSetAttribute(scores_kernel,
                         cudaFuncAttributeMaxDynamicSharedMemorySize, SMEM_SZ);
    cudaStreamCreateWithFlags(&sB, cudaStreamNonBlocking);
    cudaEventCreateWithFlags(&evFork, cudaEventDisableTiming);
    cudaEventCreateWithFlags(&evJoin, cudaEventDisableTiming);
    g_init = true;
}

extern "C" void kernel_launch(void* const* d_in, const int* in_sizes, int n_in,
                              void* d_out, int out_size) {
    const float* node_embedding = (const float*)d_in[0];
    const float* emb_weight     = (const float*)d_in[1];
    const float* itemset_len    = (const float*)d_in[2];
    const float* in_proj_w      = (const float*)d_in[3];
    const float* in_proj_b      = (const float*)d_in[4];
    const float* out_proj_w     = (const float*)d_in[5];
    const float* out_proj_b     = (const float*)d_in[6];
    const float* d1_w           = (const float*)d_in[7];
    const float* d1_b           = (const float*)d_in[8];
    const float* d2_w           = (const float*)d_in[9];
    const float* d2_b           = (const float*)d_in[10];
    const float* W3_w           = (const float*)d_in[11];
    const float* W3_b           = (const float*)d_in[12];
    const int*   sequence       = (const int*)d_in[14];
    const int*   cue            = (const int*)d_in[16];

    resolve_once();
    float* out = (float*)d_out;

    // Fork: B-side split runs on side stream, concurrent with
    // transpose -> chain -> yhat on the main (capturing) stream.
    cudaEventRecord(evFork, 0);
    cudaStreamWaitEvent(sB, evFork, 0);
    conv_split<<<(VOC*HD/4 + 255)/256, 256, 0, sB>>>(emb_weight, pBh, pBl,
                                                     VOC*HD/4);
    cudaEventRecord(evJoin, sB);

    // Main stream: weight transpose -> SAN chain (-> g_sh/g_Ah/g_Al) -> yhat
    transpose_w<<<dim3(16, 8, 5), 256>>>(in_proj_w + 2*HD*HD, out_proj_w,
                                         d1_w, d2_w, W3_w);
    chain_kernel<<<BSESS/8, 256>>>(node_embedding, itemset_len, sequence,
                                   in_proj_b + 2*HD, out_proj_b,
                                   d1_b, d2_b, W3_b);
    yhat_kernel<<<BSESS, HD>>>(emb_weight, cue, out);

    // Join: scores needs both the chain outputs and the B-side split.
    cudaStreamWaitEvent(0, evJoin, 0);
    scores_kernel<<<dim3(8, (VOC + 127)/128), 256, SMEM_SZ>>>(out + BSESS);
}

// round 13
// speedup vs baseline: 1.7016x; 1.0122x over previous
#include <cuda_runtime.h>
#include <cuda_bf16.h>
#include <cstdint>

// Problem constants
#define BSESS 1024
#define NNODE 32
#define SLEN  50
#define HD    256
#define VOC   50000

// Scores GEMM config: C[1024,50000] split-bf16.
#define KC      64
#define NCHUNK  8
#define TILEB   16384              // 128 rows x 128 B
#define STAGE3  (3*TILEB)          // B + Ah + Al = 48 KB
#define SMEM_SZ (2*STAGE3)         // 96 KB double buffered

#define W3OFF   262144             // float offset of W3^T inside g_Wt
#define CONVC   296                // conv_split CTAs (2/SM, co-residable)

// Scratch
__device__ float g_sh[BSESS*HD];
__device__ float g_Wt[4*HD*HD + 2*HD*HD];   // 4 SAN mats + W3 (512x256)
__device__ __nv_bfloat16 g_Bh[(size_t)VOC*HD];
__device__ __nv_bfloat16 g_Bl[(size_t)VOC*HD];
__device__ __nv_bfloat16 g_Ah[BSESS*HD];
__device__ __nv_bfloat16 g_Al[BSESS*HD];

// ---------------------------------------------------------------------------
// Helpers (baseline ISA only)
// ---------------------------------------------------------------------------
__device__ __forceinline__ uint32_t smem_u32(const void* p) {
    uint32_t a;
    asm("{ .reg .u64 t; cvta.to.shared.u64 t, %1; cvt.u32.u64 %0, t; }"
        : "=r"(a) : "l"(p));
    return a;
}
__device__ __forceinline__ void cp16(uint32_t dst, const void* src) {
    asm volatile("cp.async.cg.shared.global [%0], [%1], 16;"
                 :: "r"(dst), "l"(src));
}
#define CP_COMMIT() asm volatile("cp.async.commit_group;" ::: "memory")
#define CP_WAIT(n)  asm volatile("cp.async.wait_group %0;" :: "n"(n) : "memory")

__device__ __forceinline__ uint32_t sw128(uint32_t x) {
    return x ^ ((x >> 3) & 0x70);
}
__device__ __forceinline__ void ldsm4(uint32_t* r, uint32_t addr) {
    asm volatile("ldmatrix.sync.aligned.m8n8.x4.shared.b16 {%0,%1,%2,%3}, [%4];"
                 : "=r"(r[0]), "=r"(r[1]), "=r"(r[2]), "=r"(r[3]) : "r"(addr));
}
__device__ __forceinline__ void mma16816(float* c, const uint32_t* a,
                                         const uint32_t* b) {
    asm volatile(
        "mma.sync.aligned.m16n8k16.row.col.f32.bf16.bf16.f32 "
        "{%0,%1,%2,%3}, {%4,%5,%6,%7}, {%8,%9}, {%0,%1,%2,%3};"
        : "+f"(c[0]), "+f"(c[1]), "+f"(c[2]), "+f"(c[3])
        : "r"(a[0]), "r"(a[1]), "r"(a[2]), "r"(a[3]), "r"(b[0]), "r"(b[1]));
}

// ---------------------------------------------------------------------------
// One-time weight transpose into packed [k][col] layout:
//   g_Wt[base + (k>>2)*1024 + col*4 + (k&3)] = W[col][k]
// ---------------------------------------------------------------------------
__global__ void transpose_w(const float* __restrict__ Wv,
                            const float* __restrict__ Wo,
                            const float* __restrict__ d1w,
                            const float* __restrict__ d2w,
                            const float* __restrict__ W3w) {
    int m = blockIdx.z;
    int kt = blockIdx.x*32, ct = blockIdx.y*32;
    const float* src; float* dst; int KD;
    if (m < 4) {
        if (kt >= 256) return;
        KD = 256; dst = g_Wt + m*65536;
        src = (m==0) ? Wv : (m==1) ? Wo : (m==2) ? d1w : d2w;
    } else {
        KD = 512; dst = g_Wt + W3OFF; src = W3w;
    }
    int x = threadIdx.x & 31, y8 = threadIdx.x >> 5;
    int k = kt + x;
    for (int i = y8; i < 32; i += 8) {
        int col = ct + i;
        dst[((k >> 2) << 10) + col*4 + (k & 3)] = src[(size_t)col*KD + k];
    }
}

// ---------------------------------------------------------------------------
// Fused chain kernel: vn gather -> 3x SAN blocks -> W3 -> s_h + A bf16 split.
// ---------------------------------------------------------------------------
__global__ void __launch_bounds__(256, 1)
chain_kernel(const float* __restrict__ node_emb,
             const float* __restrict__ itemset_len,
             const int*   __restrict__ sequence,
             const float* __restrict__ bv,  const float* __restrict__ bo,
             const float* __restrict__ d1b, const float* __restrict__ d2b,
             const float* __restrict__ W3b) {
    __shared__ float sv[8*HD];
    __shared__ float sx[8*HD];
    __shared__ float sa[8*HD];
    __shared__ float st[8*HD];
    int tid = threadIdx.x, w = tid >> 5, lane = tid & 31;
    int b0 = blockIdx.x * 8;

    // v_n gather: warp w -> row w
    {
        int b = b0 + w;
        int t = b*SLEN + (SLEN-1);
        int s0 = sequence[t*3+0], s1 = sequence[t*3+1], s2 = sequence[t*3+2];
        float inv = 1.f / itemset_len[t];
        const float* base = node_emb + (size_t)b*NNODE*HD;
        #pragma unroll
        for (int p = 0; p < 2; p++) {
            int c = lane*8 + p*4;
            float4 acc = make_float4(0.f, 0.f, 0.f, 0.f);
            if (s0 != NNODE) { float4 v = *(const float4*)&base[s0*HD + c];
                acc.x+=v.x; acc.y+=v.y; acc.z+=v.z; acc.w+=v.w; }
            if (s1 != NNODE) { float4 v = *(const float4*)&base[s1*HD + c];
                acc.x+=v.x; acc.y+=v.y; acc.z+=v.z; acc.w+=v.w; }
            if (s2 != NNODE) { float4 v = *(const float4*)&base[s2*HD + c];
                acc.x+=v.x; acc.y+=v.y; acc.z+=v.z; acc.w+=v.w; }
            acc.x*=inv; acc.y*=inv; acc.z*=inv; acc.w*=inv;
            *(float4*)&sv[w*HD + c] = acc;
            *(float4*)&sx[w*HD + c] = acc;
        }
    }
    __syncthreads();

    const float* btab[4] = {bv, bo, d1b, d2b};
    const float* intab[4]  = {sx, st, sa, st};
    float*       outtab[4] = {st, sa, st, sx};

    for (int j = 0; j <= 12; j++) {
        bool w3 = (j == 12);
        int p = j & 3;
        const float* wt = w3 ? (g_Wt + W3OFF) : (g_Wt + p*65536);
        int nc = w3 ? 16 : 8;
        const float* in_s = intab[p];
        float* out_s = outtab[p];

        float acc[8];
        #pragma unroll
        for (int r = 0; r < 8; r++) acc[r] = 0.f;

        float4 wc[8], wn[8];
        #pragma unroll
        for (int q = 0; q < 8; q++)
            wc[q] = *(const float4*)&wt[(size_t)q*1024 + tid*4];

        for (int c = 0; c < nc; c++) {
            if (c + 1 < nc) {
                #pragma unroll
                for (int q = 0; q < 8; q++)
                    wn[q] = *(const float4*)&wt[(size_t)((c+1)*8 + q)*1024
                                                + tid*4];
            }
            const float* in = w3 ? ((c < 8) ? sv : sx) : in_s;
            int l0 = (c & 7)*32;
            #pragma unroll
            for (int q = 0; q < 8; q++) {
                #pragma unroll
                for (int r = 0; r < 8; r++) {
                    float4 a = *(const float4*)&in[r*HD + l0 + q*4];
                    acc[r] += a.x*wc[q].x + a.y*wc[q].y
                            + a.z*wc[q].z + a.w*wc[q].w;
                }
            }
            if (c + 1 < nc) {
                #pragma unroll
                for (int q = 0; q < 8; q++) wc[q] = wn[q];
            }
        }

        if (!w3) {
            float bias = btab[p][tid];
            #pragma unroll
            for (int r = 0; r < 8; r++) {
                float v = acc[r] + bias;
                if (p == 2) v = fmaxf(v, 0.f);
                if (p == 3) v += sa[r*HD + tid];
                out_s[r*HD + tid] = v;
            }
            __syncthreads();
        } else {
            float bias = W3b[tid];
            #pragma unroll
            for (int r = 0; r < 8; r++) {
                int gr = b0 + r;
                float v = acc[r] + bias;
                g_sh[gr*HD + tid] = v;
                __nv_bfloat16 h = __float2bfloat16(v);
                __nv_bfloat16 l = __float2bfloat16(v - __bfloat162float(h));
                g_Ah[gr*HD + tid] = h;
                g_Al[gr*HD + tid] = l;
            }
        }
    }
}

// ---------------------------------------------------------------------------
// fp32 -> (bf16 hi, bf16 lo) split (B side). Grid-stride with few CTAs so it
// CO-RESIDES with chain_kernel instead of flooding the SMs.
// ---------------------------------------------------------------------------
__global__ void __launch_bounds__(256)
conv_split(const float* __restrict__ src,
           __nv_bfloat16* __restrict__ hi,
           __nv_bfloat16* __restrict__ lo, int n4) {
    for (int i = blockIdx.x*256 + threadIdx.x; i < n4; i += CONVC*256) {
        float4 v = ((const float4*)src)[i];
        __nv_bfloat16 h0 = __float2bfloat16(v.x), h1 = __float2bfloat16(v.y),
                      h2 = __float2bfloat16(v.z), h3 = __float2bfloat16(v.w);
        __nv_bfloat16 l0 = __float2bfloat16(v.x - __bfloat162float(h0));
        __nv_bfloat16 l1 = __float2bfloat16(v.y - __bfloat162float(h1));
        __nv_bfloat16 l2 = __float2bfloat16(v.z - __bfloat162float(h2));
        __nv_bfloat16 l3 = __float2bfloat16(v.w - __bfloat162float(h3));
        ((__nv_bfloat162*)hi)[i*2+0] = __nv_bfloat162(h0, h1);
        ((__nv_bfloat162*)hi)[i*2+1] = __nv_bfloat162(h2, h3);
        ((__nv_bfloat162*)lo)[i*2+0] = __nv_bfloat162(l0, l1);
        ((__nv_bfloat162*)lo)[i*2+1] = __nv_bfloat162(l2, l3);
    }
}

// ---------------------------------------------------------------------------
// Scores GEMM (mma.sync bf16, split-fp32). grid (8 m-tiles, 391 n-tiles).
// ---------------------------------------------------------------------------
__global__ void __launch_bounds__(256, 2)
scores_kernel(float* __restrict__ out) {
    extern __shared__ char smem[];
    uint32_t sb = smem_u32(smem);
    int tid = threadIdx.x, lane = tid & 31, wid = tid >> 5;
    int wm = wid >> 2, wn = wid & 3;
    int m0 = blockIdx.x * 128, n0 = blockIdx.y * 128;
    int q = lane >> 3, r8 = lane & 7;

    uint32_t a_row = (uint32_t)(wm*64 + (q & 1)*8 + r8);
    uint32_t a_kb  = (uint32_t)((q >> 1) * 16);
    uint32_t b_row = (uint32_t)(wn*32 + (q >> 1)*8 + r8);
    uint32_t b_kb  = (uint32_t)((q & 1) * 16);

    float c[4][4][4];
    #pragma unroll
    for (int i = 0; i < 4; i++)
        #pragma unroll
        for (int j = 0; j < 4; j++)
            #pragma unroll
            for (int k = 0; k < 4; k++) c[i][j][k] = 0.f;

    auto load_stage = [&](int kc, int st) {
        bool hiterm = (kc < 4);
        const __nv_bfloat16* Bsrc = hiterm ? g_Bh : g_Bl;
        int k0 = (kc & 3) * KC;
        uint32_t base = sb + st*STAGE3;
        #pragma unroll
        for (int j = tid; j < 1024; j += 256) {
            int row = j >> 3, seg = j & 7;
            uint32_t off = sw128((uint32_t)(row*128 + seg*16));
            int gr = n0 + row; if (gr > VOC-1) gr = VOC-1;
            cp16(base + off, Bsrc + (size_t)gr*HD + k0 + seg*8);
            cp16(base + TILEB + off, g_Ah + (size_t)(m0 + row)*HD + k0 + seg*8);
            if (hiterm)
                cp16(base + 2*TILEB + off,
                     g_Al + (size_t)(m0 + row)*HD + k0 + seg*8);
        }
    };

    load_stage(0, 0);
    CP_COMMIT();

    for (int kc = 0; kc < NCHUNK; kc++) {
        int st = kc & 1;
        if (kc + 1 < NCHUNK) {
            load_stage(kc + 1, st ^ 1);
            CP_COMMIT();
            CP_WAIT(1);
        } else {
            CP_WAIT(0);
        }
        __syncthreads();
        uint32_t base = sb + st*STAGE3;
        bool hiterm = (kc < 4);
        #pragma unroll
        for (int ks = 0; ks < 4; ks++) {
            uint32_t b[4][2];
            #pragma unroll
            for (int nb = 0; nb < 2; nb++) {
                uint32_t r[4];
                ldsm4(r, base + sw128((b_row + nb*16)*128 + b_kb + ks*32));
                b[nb*2+0][0] = r[0]; b[nb*2+0][1] = r[1];
                b[nb*2+1][0] = r[2]; b[nb*2+1][1] = r[3];
            }
            #pragma unroll
            for (int mb = 0; mb < 4; mb++) {
                uint32_t asw = sw128((a_row + mb*16)*128 + a_kb + ks*32);
                uint32_t a[4];
                ldsm4(a, base + TILEB + asw);
                #pragma unroll
                for (int n8 = 0; n8 < 4; n8++)
                    mma16816(c[mb][n8], a, b[n8]);
                if (hiterm) {
                    uint32_t al[4];
                    ldsm4(al, base + 2*TILEB + asw);
                    #pragma unroll
                    for (int n8 = 0; n8 < 4; n8++)
                        mma16816(c[mb][n8], al, b[n8]);
                }
            }
        }
        __syncthreads();
    }

    #pragma unroll
    for (int mb = 0; mb < 4; mb++) {
        int gr0 = m0 + wm*64 + mb*16 + (lane >> 2);
        #pragma unroll
        for (int n8 = 0; n8 < 4; n8++) {
            int col = n0 + wn*32 + n8*8 + (lane & 3)*2;
            if (col < VOC) {
                *(float2*)&out[(size_t)gr0*VOC + col]     =
                    make_float2(c[mb][n8][0], c[mb][n8][1]);
                *(float2*)&out[(size_t)(gr0+8)*VOC + col] =
                    make_float2(c[mb][n8][2], c[mb][n8][3]);
            }
        }
    }
}

// ---------------------------------------------------------------------------
// y_hat[b] = dot(s_h[b], emb_weight[cue[b]])  (exact fp32 path)
// ---------------------------------------------------------------------------
__global__ void yhat_kernel(const float* __restrict__ emb,
                            const int*   __restrict__ cue,
                            float* __restrict__ out) {
    int b = blockIdx.x, tid = threadIdx.x;
    float v = g_sh[b*HD + tid] * emb[((size_t)cue[b])*HD + tid];
    #pragma unroll
    for (int o = 16; o > 0; o >>= 1) v += __shfl_down_sync(0xffffffffu, v, o);
    __shared__ float red[8];
    if ((tid & 31) == 0) red[tid >> 5] = v;
    __syncthreads();
    if (tid == 0) {
        float s = 0.f;
        #pragma unroll
        for (int i = 0; i < 8; i++) s += red[i];
        out[b] = s;
    }
}

// ---------------------------------------------------------------------------
static __nv_bfloat16 *pBh, *pBl;
static cudaStream_t sB = nullptr;
static cudaEvent_t evFork = nullptr, evConv = nullptr,
                   evChain = nullptr, evSide = nullptr;
static bool g_init = false;

static void resolve_once() {
    if (g_init) return;
    cudaGetSymbolAddress((void**)&pBh, g_Bh);
    cudaGetSymbolAddress((void**)&pBl, g_Bl);
    cudaFuncSetAttribute(scores_kernel,
                         cudaFuncAttributeMaxDynamicSharedMemorySize, SMEM_SZ);
    cudaStreamCreateWithFlags(&sB, cudaStreamNonBlocking);
    cudaEventCreateWithFlags(&evFork,  cudaEventDisableTiming);
    cudaEventCreateWithFlags(&evConv,  cudaEventDisableTiming);
    cudaEventCreateWithFlags(&evChain, cudaEventDisableTiming);
    cudaEventCreateWithFlags(&evSide,  cudaEventDisableTiming);
    g_init = true;
}

extern "C" void kernel_launch(void* const* d_in, const int* in_sizes, int n_in,
                              void* d_out, int out_size) {
    const float* node_embedding = (const float*)d_in[0];
    const float* emb_weight     = (const float*)d_in[1];
    const float* itemset_len    = (const float*)d_in[2];
    const float* in_proj_w      = (const float*)d_in[3];
    const float* in_proj_b      = (const float*)d_in[4];
    const float* out_proj_w     = (const float*)d_in[5];
    const float* out_proj_b     = (const float*)d_in[6];
    const float* d1_w           = (const float*)d_in[7];
    const float* d1_b           = (const float*)d_in[8];
    const float* d2_w           = (const float*)d_in[9];
    const float* d2_b           = (const float*)d_in[10];
    const float* W3_w           = (const float*)d_in[11];
    const float* W3_b           = (const float*)d_in[12];
    const int*   sequence       = (const int*)d_in[14];
    const int*   cue            = (const int*)d_in[16];

    resolve_once();
    float* out = (float*)d_out;

    // Fork: conv_split (296 grid-stride CTAs, co-residable) on side stream.
    cudaEventRecord(evFork, 0);
    cudaStreamWaitEvent(sB, evFork, 0);
    conv_split<<<CONVC, 256, 0, sB>>>(emb_weight, pBh, pBl, VOC*HD/4);
    cudaEventRecord(evConv, sB);

    // Main: weight transpose -> SAN chain (writes g_sh/g_Ah/g_Al).
    transpose_w<<<dim3(16, 8, 5), 256>>>(in_proj_w + 2*HD*HD, out_proj_w,
                                         d1_w, d2_w, W3_w);
    chain_kernel<<<BSESS/8, 256>>>(node_embedding, itemset_len, sequence,
                                   in_proj_b + 2*HD, out_proj_b,
                                   d1_b, d2_b, W3_b);
    cudaEventRecord(evChain, 0);

    // Side: yhat (needs chain) overlaps with scores.
    cudaStreamWaitEvent(sB, evChain, 0);
    yhat_kernel<<<BSESS, HD, 0, sB>>>(emb_weight, cue, out);
    cudaEventRecord(evSide, sB);

    // Main: scores (needs chain outputs + conv outputs).
    cudaStreamWaitEvent(0, evConv, 0);
    scores_kernel<<<dim3(8, (VOC + 127)/128), 256, SMEM_SZ>>>(out + BSESS);

    // Join side stream back into the capture-origin stream.
    cudaStreamWaitEvent(0, evSide, 0);
}